// round 14
// baseline (speedup 1.0000x reference)
#include <cuda_runtime.h>
#include <cuda_fp16.h>
#include <math.h>
#include <stdint.h>

#define BMAX    8192
#define DDIM    128
#define MARGIN  0.5f
#define BM      128
#define BN      128
#define CHUNK   4             // column tiles per work item
#define THREADS 256
#define GRID_P  296           // persistent CTAs (148 SMs x 2)

#define ENC_NEGINF 0x007FFFFFu   // enc(-inf)
#define ENC_POSINF 0xFF800000u   // enc(+inf)

// ---------------- device globals -------------------------------------------
__device__ __half g_hi[BMAX * DDIM];
__device__ float g_sqn[BMAX];
__device__ unsigned int g_posE[BMAX];
__device__ unsigned int g_negE[BMAX];
__device__ unsigned int g_ctr;

// ---------------- smem byte offsets ----------------------------------------
#define OFF_AHI    0            // 128*256 = 32768
#define OFF_B0     32768
#define OFF_B1     65536
#define OFF_SQALL  98304        // CHUNK*128 floats = 2048B
#define OFF_LBLALL 100352       // CHUNK*128 ints   = 2048B
#define OFF_COLP   102400       // 8*128 floats = 4096B (also work-item slot)
#define OFF_COLN   106496       // 4096B
#define SMEM_SZ    110592       // 108 KB -> 2 CTAs/SM

// ---------------- PTX helpers ----------------------------------------------
__device__ __forceinline__ uint32_t smem_u32(const void* p) {
    uint32_t a;
    asm("{ .reg .u64 t; cvta.to.shared.u64 t, %1; cvt.u32.u64 %0, t; }"
        : "=r"(a) : "l"(p));
    return a;
}
__device__ __forceinline__ void cpa16(uint32_t dst, const void* src) {
    asm volatile("cp.async.cg.shared.global [%0], [%1], 16;"
                 :: "r"(dst), "l"(__cvta_generic_to_global(src)));
}
__device__ __forceinline__ void cpa_commit() {
    asm volatile("cp.async.commit_group;" ::: "memory");
}
template <int N>
__device__ __forceinline__ void cpa_wait() {
    asm volatile("cp.async.wait_group %0;" :: "n"(N) : "memory");
}
__device__ __forceinline__ void ldsm4(uint32_t* r, uint32_t addr) {
    asm volatile("ldmatrix.sync.aligned.m8n8.x4.shared.b16 {%0,%1,%2,%3}, [%4];"
                 : "=r"(r[0]), "=r"(r[1]), "=r"(r[2]), "=r"(r[3]) : "r"(addr));
}
__device__ __forceinline__ void mma_f16(float* c, const uint32_t* a,
                                        const uint32_t* b) {
    asm volatile(
        "mma.sync.aligned.m16n8k16.row.col.f32.f16.f16.f32 "
        "{%0,%1,%2,%3}, {%4,%5,%6,%7}, {%8,%9}, {%0,%1,%2,%3};"
        : "+f"(c[0]), "+f"(c[1]), "+f"(c[2]), "+f"(c[3])
        : "r"(a[0]), "r"(a[1]), "r"(a[2]), "r"(a[3]), "r"(b[0]), "r"(b[1]));
}
__device__ __forceinline__ uint32_t swz(uint32_t base, int row, int c) {
    return base + (uint32_t)(row * 256) + (uint32_t)(((c ^ (row & 7)) << 4));
}
// order-preserving float<->uint encode for atomic max/min
__device__ __forceinline__ unsigned int encf(float f) {
    unsigned int u = __float_as_uint(f);
    return (u & 0x80000000u) ? ~u : (u | 0x80000000u);
}
__device__ __forceinline__ float decf(unsigned int e) {
    unsigned int u = (e & 0x80000000u) ? (e ^ 0x80000000u) : ~e;
    return __uint_as_float(u);
}

// ---------------------------------------------------------------------------
// Kernel 0: fp32 -> fp16 + squared norms + result-buffer / counter init.
// ---------------------------------------------------------------------------
__global__ void convert_kernel(const float* __restrict__ emb, int B) {
    int warp = (blockIdx.x * blockDim.x + threadIdx.x) >> 5;
    int lane = threadIdx.x & 31;
    if (warp >= B) return;
    const float4* row = (const float4*)(emb + (size_t)warp * DDIM);
    float4 v = row[lane];
    float s = v.x * v.x + v.y * v.y + v.z * v.z + v.w * v.w;
    #pragma unroll
    for (int off = 16; off; off >>= 1) s += __shfl_xor_sync(0xffffffffu, s, off);
    if (lane == 0) g_sqn[warp] = s;
    if (lane == 1) g_posE[warp] = ENC_NEGINF;
    if (lane == 2) g_negE[warp] = ENC_POSINF;
    if (warp == 0 && lane == 3) g_ctr = 0;      // reset persistent scheduler

    __half2* hp = (__half2*)(g_hi + (size_t)warp * DDIM + lane * 4);
    hp[0] = __halves2half2(__float2half_rn(v.x), __float2half_rn(v.y));
    hp[1] = __halves2half2(__float2half_rn(v.z), __float2half_rn(v.w));
}

// ---------------------------------------------------------------------------
// B tile loader (cp.async, swizzled). B data only — metadata is separate.
// ---------------------------------------------------------------------------
__device__ __forceinline__ void load_btile(uint32_t sbase, int which, int c0,
                                           int tid) {
    uint32_t off_b = which ? OFF_B1 : OFF_B0;
    #pragma unroll
    for (int i = 0; i < 8; i++) {
        int chunk = tid + i * THREADS;        // 0..2047
        int row = chunk >> 4;
        int c   = chunk & 15;
        cpa16(swz(sbase + off_b, row, c),
              g_hi + (size_t)(c0 + row) * DDIM + c * 8);
    }
}

// ---------------------------------------------------------------------------
// Kernel 1: persistent upper-triangle fp16 Gram + two-direction mining.
// Work item = (row block rb, up to CHUNK column tiles cb >= rb), fetched
// dynamically via a global counter. 2 CTAs/SM.
// ---------------------------------------------------------------------------
__global__ __launch_bounds__(THREADS, 2)
void tile_kernel(const int* __restrict__ labels, int B, int nItems) {
    extern __shared__ char smem[];
    const uint32_t sbase = smem_u32(smem);
    const int tid  = threadIdx.x;
    const int lane = tid & 31;
    const int wid  = tid >> 5;
    const int wm   = wid & 3;
    const int wn   = wid >> 2;
    const int NB   = B / BM;

    float* sq_all  = (float*)(smem + OFF_SQALL);
    int*   lbl_all = (int*)(smem + OFF_LBLALL);
    float* colP = (float*)(smem + OFF_COLP);
    float* colN = (float*)(smem + OFF_COLN);
    int*   itemSlot = (int*)(smem + OFF_COLP);   // reused before colP writes

    const int aRow = (lane & 15);
    const int aCb  = (lane >> 4);
    const int bRow = (lane & 7) + ((lane >> 4) << 3);
    const int bCb  = (lane >> 3) & 1;
    const int g  = lane >> 2;
    const int t4 = lane & 3;
    const bool partialLane = ((lane & 12) == 0);       // g==0 or g==4
    const int partRow = wm * 2 + (lane >> 4);          // 0..7

    int prev_rb = -1;
    int rowsG[4]; int labR[4]; float sqR[4];

    for (;;) {
        // ---- fetch next work item (barrier also drains prior item) -----
        if (tid == 0) itemSlot[0] = (int)atomicAdd(&g_ctr, 1u);
        __syncthreads();
        const int item = itemSlot[0];
        if (item >= nItems) break;

        // map item -> (rb, chunk)
        int rb = 0, rem = item;
        for (;;) {
            int ch = (NB - rb + CHUNK - 1) / CHUNK;
            if (rem < ch) break;
            rem -= ch; rb++;
        }
        const int cb0 = rb + rem * CHUNK;
        const int nt = min(CHUNK, NB - cb0);
        const int r0 = rb * BM;

        // ---- prologue: A (if row changed) + B(0) group0, B(1) group1 ---
        if (rb != prev_rb) {
            #pragma unroll
            for (int i = 0; i < 8; i++) {
                int chunk = tid + i * THREADS;
                int row = chunk >> 4;
                int c   = chunk & 15;
                cpa16(swz(sbase + OFF_AHI, row, c),
                      g_hi + (size_t)(r0 + row) * DDIM + c * 8);
            }
            #pragma unroll
            for (int s = 0; s < 4; s++) {
                int rl = wm * 32 + (s >> 1) * 16 + (s & 1) * 8 + g;
                rowsG[s] = r0 + rl;
                labR[s]  = labels[r0 + rl];
                sqR[s]   = g_sqn[r0 + rl];
            }
            prev_rb = rb;
        }
        load_btile(sbase, 0, cb0 * BN, tid);
        cpa_commit();                              // group: (A?) + B0
        if (nt > 1) load_btile(sbase, 1, (cb0 + 1) * BN, tid);
        cpa_commit();                              // group: B1 (may be empty)

        // column metadata for this item
        for (int i = tid; i < nt * BN; i += THREADS) {
            sq_all[i]  = g_sqn[cb0 * BN + i];
            lbl_all[i] = labels[cb0 * BN + i];
        }

        float pos[4], neg[4];
        #pragma unroll
        for (int s = 0; s < 4; s++) { pos[s] = -INFINITY; neg[s] = INFINITY; }

        // ---- tiles of this item -----------------------------------------
        for (int t = 0; t < nt; t++) {
            cpa_wait<1>();
            __syncthreads();

            const int which = t & 1;
            const uint32_t bBase = sbase + (which ? OFF_B1 : OFF_B0);
            const float* sq_s  = sq_all + t * BN;
            const int*   lbl_s = lbl_all + t * BN;
            const int cb = cb0 + t;
            const bool diag = (cb == rb);
            const int cg0 = cb * BN;

            float acc[2][8][4];
            #pragma unroll
            for (int mi = 0; mi < 2; mi++)
                #pragma unroll
                for (int ni = 0; ni < 8; ni++)
                    #pragma unroll
                    for (int q = 0; q < 4; q++) acc[mi][ni][q] = 0.f;

            #pragma unroll
            for (int ks = 0; ks < 8; ks++) {
                uint32_t ahi[2][4], bhi[4][4];
                #pragma unroll
                for (int mi = 0; mi < 2; mi++) {
                    int row = wm * 32 + mi * 16 + aRow;
                    ldsm4(ahi[mi], swz(sbase + OFF_AHI, row, ks * 2 + aCb));
                }
                #pragma unroll
                for (int nj = 0; nj < 4; nj++) {
                    int row = wn * 64 + nj * 16 + bRow;
                    ldsm4(bhi[nj], swz(bBase, row, ks * 2 + bCb));
                }
                #pragma unroll
                for (int mi = 0; mi < 2; mi++)
                    #pragma unroll
                    for (int ni = 0; ni < 8; ni++)
                        mma_f16(acc[mi][ni], ahi[mi],
                                &bhi[ni >> 1][(ni & 1) * 2]);
            }

            // buffer consumed; prefetch t+2 so latency overlaps mining
            __syncthreads();
            if (t + 2 < nt)
                load_btile(sbase, which, (cb0 + t + 2) * BN, tid);
            cpa_commit();   // uniform group counting

            if (diag) {
                // ---- diagonal: row mining only, self-exclusion ---------
                #pragma unroll
                for (int ni = 0; ni < 8; ni++) {
                    int colLoc = wn * 64 + ni * 8 + t4 * 2;
                    float sq0 = sq_s[colLoc], sq1 = sq_s[colLoc + 1];
                    int   l0  = lbl_s[colLoc], l1 = lbl_s[colLoc + 1];
                    int   j0  = cg0 + colLoc;
                    #pragma unroll
                    for (int s = 0; s < 4; s++) {
                        float v0 = fmaf(-2.f, acc[s >> 1][ni][(s & 1) * 2], sq0);
                        float v1 = fmaf(-2.f, acc[s >> 1][ni][(s & 1) * 2 + 1], sq1);
                        if (l0 == labR[s]) {
                            if (j0 != rowsG[s]) pos[s] = fmaxf(pos[s], v0);
                        } else neg[s] = fminf(neg[s], v0);
                        if (l1 == labR[s]) {
                            if (j0 + 1 != rowsG[s]) pos[s] = fmaxf(pos[s], v1);
                        } else neg[s] = fminf(neg[s], v1);
                    }
                }
            } else {
                // ---- off-diagonal: merged row+col, 2-stage shfl --------
                #pragma unroll
                for (int ni = 0; ni < 8; ni++) {
                    #pragma unroll
                    for (int v = 0; v < 2; v++) {
                        int colLoc = wn * 64 + ni * 8 + t4 * 2 + v;
                        float sqj = sq_s[colLoc];
                        int   lj  = lbl_s[colLoc];
                        float cp = -INFINITY, cn = INFINITY;
                        #pragma unroll
                        for (int s = 0; s < 4; s++) {
                            float a = acc[s >> 1][ni][(s & 1) * 2 + v];
                            float vrow = fmaf(-2.f, a, sqj);
                            float vcol = fmaf(-2.f, a, sqR[s]);
                            if (lj == labR[s]) {
                                pos[s] = fmaxf(pos[s], vrow);
                                cp = fmaxf(cp, vcol);
                            } else {
                                neg[s] = fminf(neg[s], vrow);
                                cn = fminf(cn, vcol);
                            }
                        }
                        cp = fmaxf(cp, __shfl_xor_sync(0xffffffffu, cp, 4));
                        cn = fminf(cn, __shfl_xor_sync(0xffffffffu, cn, 4));
                        cp = fmaxf(cp, __shfl_xor_sync(0xffffffffu, cp, 8));
                        cn = fminf(cn, __shfl_xor_sync(0xffffffffu, cn, 8));
                        if (partialLane) {
                            colP[partRow * 128 + colLoc] = cp;
                            colN[partRow * 128 + colLoc] = cn;
                        }
                    }
                }
                __syncthreads();
                if (tid < 128) {
                    float p = colP[tid];
                    #pragma unroll
                    for (int w = 1; w < 8; w++)
                        p = fmaxf(p, colP[w * 128 + tid]);
                    atomicMax(&g_posE[cg0 + tid], encf(p));
                } else {
                    int c = tid - 128;
                    float n = colN[c];
                    #pragma unroll
                    for (int w = 1; w < 8; w++)
                        n = fminf(n, colN[w * 128 + c]);
                    atomicMin(&g_negE[cg0 + c], encf(n));
                }
            }
        }

        // ---- flush row results for this item ---------------------------
        #pragma unroll
        for (int s = 0; s < 4; s++) {
            #pragma unroll
            for (int off = 1; off < 4; off <<= 1) {
                pos[s] = fmaxf(pos[s], __shfl_xor_sync(0xffffffffu, pos[s], off));
                neg[s] = fminf(neg[s], __shfl_xor_sync(0xffffffffu, neg[s], off));
            }
        }
        if (t4 == 0) {
            #pragma unroll
            for (int s = 0; s < 4; s++) {
                atomicMax(&g_posE[rowsG[s]], encf(pos[s]));
                atomicMin(&g_negE[rowsG[s]], encf(neg[s]));
            }
        }
    }
}

// ---------------------------------------------------------------------------
// Kernel 2: decode, per-anchor loss, global mean.
// ---------------------------------------------------------------------------
__global__ void finalize_kernel(int B, float* __restrict__ out) {
    __shared__ float ssum[1024];
    __shared__ float scnt[1024];
    int tid = threadIdx.x;
    float sum = 0.f, cnt = 0.f;
    for (int r = tid; r < B; r += 1024) {
        float p = decf(g_posE[r]);
        float n = decf(g_negE[r]);
        bool valid = (p != -INFINITY) && (n != INFINITY);
        float sq = g_sqn[r];
        float hp = sqrtf(fmaxf(sq + p, 0.f));
        float hn = sqrtf(fmaxf(sq + n, 0.f));
        float per = fmaxf(hp - hn + MARGIN, 0.f);
        if (valid) { sum += per; cnt += 1.f; }
    }
    ssum[tid] = sum;
    scnt[tid] = cnt;
    __syncthreads();
    for (int s = 512; s; s >>= 1) {
        if (tid < s) { ssum[tid] += ssum[tid + s]; scnt[tid] += scnt[tid + s]; }
        __syncthreads();
    }
    if (tid == 0) out[0] = ssum[0] / fmaxf(scnt[0], 1.f);
}

// ---------------------------------------------------------------------------
extern "C" void kernel_launch(void* const* d_in, const int* in_sizes, int n_in,
                              void* d_out, int out_size) {
    const float* emb    = (const float*)d_in[0];
    const int*   labels = (const int*)d_in[1];
    const int B = in_sizes[1];                   // 8192
    float* out = (float*)d_out;

    cudaFuncSetAttribute(tile_kernel,
                         cudaFuncAttributeMaxDynamicSharedMemorySize, SMEM_SZ);

    convert_kernel<<<(B * 32 + 255) / 256, 256>>>(emb, B);

    const int NB = B / BM;
    int nItems = 0;
    for (int rb = 0; rb < NB; rb++) nItems += (NB - rb + CHUNK - 1) / CHUNK;

    int grid = nItems < GRID_P ? nItems : GRID_P;
    tile_kernel<<<grid, THREADS, SMEM_SZ>>>(labels, B, nItems);

    finalize_kernel<<<1, 1024>>>(B, out);
}

// round 15
// speedup vs baseline: 1.0799x; 1.0799x over previous
#include <cuda_runtime.h>
#include <cuda_fp16.h>
#include <math.h>
#include <stdint.h>

#define BMAX    8192
#define DDIM    128
#define MARGIN  0.5f
#define BM      128
#define BN      128
#define CHUNK   8             // column tiles per CTA
#define THREADS 256

#define ENC_NEGINF 0x007FFFFFu   // enc(-inf)
#define ENC_POSINF 0xFF800000u   // enc(+inf)

// ---------------- device globals -------------------------------------------
__device__ __half g_hi[BMAX * DDIM];
__device__ float g_sqn[BMAX];
__device__ unsigned int g_posE[BMAX];
__device__ unsigned int g_negE[BMAX];

// ---------------- smem byte offsets ----------------------------------------
#define OFF_AHI    0            // 128*256 = 32768
#define OFF_B0     32768
#define OFF_B1     65536
#define OFF_SQALL  98304        // CHUNK*128 floats = 4096B
#define OFF_LBLALL 102400       // CHUNK*128 ints   = 4096B
#define OFF_COLP   106496       // 8*128 floats = 4096B
#define OFF_COLN   110592       // 4096B
#define SMEM_SZ    114688       // 112 KB -> still 2 CTAs/SM (224KB+rsv < 228KB)

// ---------------- PTX helpers ----------------------------------------------
__device__ __forceinline__ uint32_t smem_u32(const void* p) {
    uint32_t a;
    asm("{ .reg .u64 t; cvta.to.shared.u64 t, %1; cvt.u32.u64 %0, t; }"
        : "=r"(a) : "l"(p));
    return a;
}
__device__ __forceinline__ void cpa16(uint32_t dst, const void* src) {
    asm volatile("cp.async.cg.shared.global [%0], [%1], 16;"
                 :: "r"(dst), "l"(__cvta_generic_to_global(src)));
}
__device__ __forceinline__ void cpa_commit() {
    asm volatile("cp.async.commit_group;" ::: "memory");
}
template <int N>
__device__ __forceinline__ void cpa_wait() {
    asm volatile("cp.async.wait_group %0;" :: "n"(N) : "memory");
}
__device__ __forceinline__ void ldsm4(uint32_t* r, uint32_t addr) {
    asm volatile("ldmatrix.sync.aligned.m8n8.x4.shared.b16 {%0,%1,%2,%3}, [%4];"
                 : "=r"(r[0]), "=r"(r[1]), "=r"(r[2]), "=r"(r[3]) : "r"(addr));
}
__device__ __forceinline__ void mma_f16(float* c, const uint32_t* a,
                                        const uint32_t* b) {
    asm volatile(
        "mma.sync.aligned.m16n8k16.row.col.f32.f16.f16.f32 "
        "{%0,%1,%2,%3}, {%4,%5,%6,%7}, {%8,%9}, {%0,%1,%2,%3};"
        : "+f"(c[0]), "+f"(c[1]), "+f"(c[2]), "+f"(c[3])
        : "r"(a[0]), "r"(a[1]), "r"(a[2]), "r"(a[3]), "r"(b[0]), "r"(b[1]));
}
__device__ __forceinline__ uint32_t swz(uint32_t base, int row, int c) {
    return base + (uint32_t)(row * 256) + (uint32_t)(((c ^ (row & 7)) << 4));
}
// order-preserving float<->uint encode for atomic max/min
__device__ __forceinline__ unsigned int encf(float f) {
    unsigned int u = __float_as_uint(f);
    return (u & 0x80000000u) ? ~u : (u | 0x80000000u);
}
__device__ __forceinline__ float decf(unsigned int e) {
    unsigned int u = (e & 0x80000000u) ? (e ^ 0x80000000u) : ~e;
    return __uint_as_float(u);
}

// ---------------------------------------------------------------------------
// Kernel 0: fp32 -> fp16 + squared norms (fp32) + result-buffer init.
// ---------------------------------------------------------------------------
__global__ void convert_kernel(const float* __restrict__ emb, int B) {
    int warp = (blockIdx.x * blockDim.x + threadIdx.x) >> 5;
    int lane = threadIdx.x & 31;
    if (warp >= B) return;
    const float4* row = (const float4*)(emb + (size_t)warp * DDIM);
    float4 v = row[lane];
    float s = v.x * v.x + v.y * v.y + v.z * v.z + v.w * v.w;
    #pragma unroll
    for (int off = 16; off; off >>= 1) s += __shfl_xor_sync(0xffffffffu, s, off);
    if (lane == 0) g_sqn[warp] = s;
    if (lane == 1) g_posE[warp] = ENC_NEGINF;
    if (lane == 2) g_negE[warp] = ENC_POSINF;

    __half2* hp = (__half2*)(g_hi + (size_t)warp * DDIM + lane * 4);
    hp[0] = __halves2half2(__float2half_rn(v.x), __float2half_rn(v.y));
    hp[1] = __halves2half2(__float2half_rn(v.z), __float2half_rn(v.w));
}

// ---------------------------------------------------------------------------
// B tile loader (cp.async, swizzled). B data only — metadata is separate.
// ---------------------------------------------------------------------------
__device__ __forceinline__ void load_btile(uint32_t sbase, int which, int c0,
                                           int tid) {
    uint32_t off_b = which ? OFF_B1 : OFF_B0;
    #pragma unroll
    for (int i = 0; i < 8; i++) {
        int chunk = tid + i * THREADS;        // 0..2047
        int row = chunk >> 4;
        int c   = chunk & 15;
        cpa16(swz(sbase + off_b, row, c),
              g_hi + (size_t)(c0 + row) * DDIM + c * 8);
    }
}

// ---------------------------------------------------------------------------
// Kernel 1: upper-triangle fp16 Gram + two-direction batch-hard mining.
// Each CTA: one row block rb, up to CHUNK column tiles cb >= rb. 2 CTAs/SM.
// ---------------------------------------------------------------------------
__global__ __launch_bounds__(THREADS, 2)
void tile_kernel(const int* __restrict__ labels, int B) {
    extern __shared__ char smem[];
    const uint32_t sbase = smem_u32(smem);
    const int tid  = threadIdx.x;
    const int lane = tid & 31;
    const int wid  = tid >> 5;
    const int wm   = wid & 3;
    const int wn   = wid >> 2;
    const int NB   = B / BM;

    // ---- map blockIdx -> (rb, chunk) ----
    int b = blockIdx.x, rb = 0;
    for (;;) {
        int ch = (NB - rb + CHUNK - 1) / CHUNK;
        if (b < ch) break;
        b -= ch; rb++;
    }
    const int cb0 = rb + b * CHUNK;
    const int nt = min(CHUNK, NB - cb0);
    const int r0 = rb * BM;

    float* sq_all  = (float*)(smem + OFF_SQALL);
    int*   lbl_all = (int*)(smem + OFF_LBLALL);
    float* colP = (float*)(smem + OFF_COLP);
    float* colN = (float*)(smem + OFF_COLN);

    // ---- prologue: A + B(0) in group0, B(1) in group1 ------------------
    #pragma unroll
    for (int i = 0; i < 8; i++) {
        int chunk = tid + i * THREADS;
        int row = chunk >> 4;
        int c   = chunk & 15;
        cpa16(swz(sbase + OFF_AHI, row, c),
              g_hi + (size_t)(r0 + row) * DDIM + c * 8);
    }
    load_btile(sbase, 0, cb0 * BN, tid);
    cpa_commit();                              // group 0
    if (nt > 1) load_btile(sbase, 1, (cb0 + 1) * BN, tid);
    cpa_commit();                              // group 1 (may be empty)

    // all column metadata for this CTA, loaded once
    for (int i = tid; i < nt * BN; i += THREADS) {
        sq_all[i]  = g_sqn[cb0 * BN + i];
        lbl_all[i] = labels[cb0 * BN + i];
    }

    // my 4 anchor rows
    const int g  = lane >> 2;
    const int t4 = lane & 3;
    int rowsG[4]; int labR[4]; float sqR[4];
    #pragma unroll
    for (int s = 0; s < 4; s++) {
        int rl = wm * 32 + (s >> 1) * 16 + (s & 1) * 8 + g;
        rowsG[s] = r0 + rl;
        labR[s]  = labels[r0 + rl];
        sqR[s]   = g_sqn[r0 + rl];
    }

    float pos[4], neg[4];
    #pragma unroll
    for (int s = 0; s < 4; s++) { pos[s] = -INFINITY; neg[s] = INFINITY; }

    const int aRow = (lane & 15);
    const int aCb  = (lane >> 4);
    const int bRow = (lane & 7) + ((lane >> 4) << 3);
    const int bCb  = (lane >> 3) & 1;
    const bool partialLane = ((lane & 12) == 0);       // g==0 or g==4
    const int partRow = wm * 2 + (lane >> 4);          // 0..7

    // ---- main loop ------------------------------------------------------
    for (int t = 0; t < nt; t++) {
        cpa_wait<1>();
        __syncthreads();

        const int which = t & 1;
        const uint32_t bBase = sbase + (which ? OFF_B1 : OFF_B0);
        const float* sq_s  = sq_all + t * BN;
        const int*   lbl_s = lbl_all + t * BN;
        const int cb = cb0 + t;
        const bool diag = (cb == rb);
        const int cg0 = cb * BN;

        float acc[2][8][4];
        #pragma unroll
        for (int mi = 0; mi < 2; mi++)
            #pragma unroll
            for (int ni = 0; ni < 8; ni++)
                #pragma unroll
                for (int q = 0; q < 4; q++) acc[mi][ni][q] = 0.f;

        #pragma unroll
        for (int ks = 0; ks < 8; ks++) {
            uint32_t ahi[2][4], bhi[4][4];
            #pragma unroll
            for (int mi = 0; mi < 2; mi++) {
                int row = wm * 32 + mi * 16 + aRow;
                ldsm4(ahi[mi], swz(sbase + OFF_AHI, row, ks * 2 + aCb));
            }
            #pragma unroll
            for (int nj = 0; nj < 4; nj++) {
                int row = wn * 64 + nj * 16 + bRow;
                ldsm4(bhi[nj], swz(bBase, row, ks * 2 + bCb));
            }
            #pragma unroll
            for (int mi = 0; mi < 2; mi++)
                #pragma unroll
                for (int ni = 0; ni < 8; ni++)
                    mma_f16(acc[mi][ni], ahi[mi], &bhi[ni >> 1][(ni & 1) * 2]);
        }

        // B buffer `which` consumed; prefetch t+2 before the epilogue so
        // the cp.async latency overlaps mining.
        __syncthreads();
        if (t + 2 < nt)
            load_btile(sbase, which, (cb0 + t + 2) * BN, tid);
        cpa_commit();   // uniform group counting

        if (diag) {
            // ---- diagonal tile: row mining only, with self-exclusion ---
            #pragma unroll
            for (int ni = 0; ni < 8; ni++) {
                int colLoc = wn * 64 + ni * 8 + t4 * 2;
                float sq0 = sq_s[colLoc], sq1 = sq_s[colLoc + 1];
                int   l0  = lbl_s[colLoc], l1 = lbl_s[colLoc + 1];
                int   j0  = cg0 + colLoc;
                #pragma unroll
                for (int s = 0; s < 4; s++) {
                    float v0 = fmaf(-2.f, acc[s >> 1][ni][(s & 1) * 2], sq0);
                    float v1 = fmaf(-2.f, acc[s >> 1][ni][(s & 1) * 2 + 1], sq1);
                    if (l0 == labR[s]) {
                        if (j0 != rowsG[s]) pos[s] = fmaxf(pos[s], v0);
                    } else neg[s] = fminf(neg[s], v0);
                    if (l1 == labR[s]) {
                        if (j0 + 1 != rowsG[s]) pos[s] = fmaxf(pos[s], v1);
                    } else neg[s] = fminf(neg[s], v1);
                }
            }
        } else {
            // ---- off-diagonal: merged row+col mining, 2-stage shfl,
            //      8 partial rows to smem, single atomic per column.
            #pragma unroll
            for (int ni = 0; ni < 8; ni++) {
                #pragma unroll
                for (int v = 0; v < 2; v++) {
                    int colLoc = wn * 64 + ni * 8 + t4 * 2 + v;
                    float sqj = sq_s[colLoc];
                    int   lj  = lbl_s[colLoc];
                    float cp = -INFINITY, cn = INFINITY;
                    #pragma unroll
                    for (int s = 0; s < 4; s++) {
                        float a = acc[s >> 1][ni][(s & 1) * 2 + v];
                        float vrow = fmaf(-2.f, a, sqj);
                        float vcol = fmaf(-2.f, a, sqR[s]);
                        if (lj == labR[s]) {
                            pos[s] = fmaxf(pos[s], vrow);
                            cp = fmaxf(cp, vcol);
                        } else {
                            neg[s] = fminf(neg[s], vrow);
                            cn = fminf(cn, vcol);
                        }
                    }
                    cp = fmaxf(cp, __shfl_xor_sync(0xffffffffu, cp, 4));
                    cn = fminf(cn, __shfl_xor_sync(0xffffffffu, cn, 4));
                    cp = fmaxf(cp, __shfl_xor_sync(0xffffffffu, cp, 8));
                    cn = fminf(cn, __shfl_xor_sync(0xffffffffu, cn, 8));
                    if (partialLane) {          // lanes g==0 and g==4
                        colP[partRow * 128 + colLoc] = cp;
                        colN[partRow * 128 + colLoc] = cn;
                    }
                }
            }
            __syncthreads();
            if (tid < 128) {
                float p = colP[tid];
                #pragma unroll
                for (int w = 1; w < 8; w++)
                    p = fmaxf(p, colP[w * 128 + tid]);
                atomicMax(&g_posE[cg0 + tid], encf(p));
            } else {
                int c = tid - 128;
                float n = colN[c];
                #pragma unroll
                for (int w = 1; w < 8; w++)
                    n = fminf(n, colN[w * 128 + c]);
                atomicMin(&g_negE[cg0 + c], encf(n));
            }
        }
    }

    // ---- row results: reduce over t4, atomic-merge ----------------------
    #pragma unroll
    for (int s = 0; s < 4; s++) {
        #pragma unroll
        for (int off = 1; off < 4; off <<= 1) {
            pos[s] = fmaxf(pos[s], __shfl_xor_sync(0xffffffffu, pos[s], off));
            neg[s] = fminf(neg[s], __shfl_xor_sync(0xffffffffu, neg[s], off));
        }
    }
    if (t4 == 0) {
        #pragma unroll
        for (int s = 0; s < 4; s++) {
            atomicMax(&g_posE[rowsG[s]], encf(pos[s]));
            atomicMin(&g_negE[rowsG[s]], encf(neg[s]));
        }
    }
}

// ---------------------------------------------------------------------------
// Kernel 2: decode, per-anchor loss, global mean.
// ---------------------------------------------------------------------------
__global__ void finalize_kernel(int B, float* __restrict__ out) {
    __shared__ float ssum[1024];
    __shared__ float scnt[1024];
    int tid = threadIdx.x;
    float sum = 0.f, cnt = 0.f;
    for (int r = tid; r < B; r += 1024) {
        float p = decf(g_posE[r]);
        float n = decf(g_negE[r]);
        bool valid = (p != -INFINITY) && (n != INFINITY);
        float sq = g_sqn[r];
        float hp = sqrtf(fmaxf(sq + p, 0.f));
        float hn = sqrtf(fmaxf(sq + n, 0.f));
        float per = fmaxf(hp - hn + MARGIN, 0.f);
        if (valid) { sum += per; cnt += 1.f; }
    }
    ssum[tid] = sum;
    scnt[tid] = cnt;
    __syncthreads();
    for (int s = 512; s; s >>= 1) {
        if (tid < s) { ssum[tid] += ssum[tid + s]; scnt[tid] += scnt[tid + s]; }
        __syncthreads();
    }
    if (tid == 0) out[0] = ssum[0] / fmaxf(scnt[0], 1.f);
}

// ---------------------------------------------------------------------------
extern "C" void kernel_launch(void* const* d_in, const int* in_sizes, int n_in,
                              void* d_out, int out_size) {
    const float* emb    = (const float*)d_in[0];
    const int*   labels = (const int*)d_in[1];
    const int B = in_sizes[1];                   // 8192
    float* out = (float*)d_out;

    cudaFuncSetAttribute(tile_kernel,
                         cudaFuncAttributeMaxDynamicSharedMemorySize, SMEM_SZ);

    convert_kernel<<<(B * 32 + 255) / 256, 256>>>(emb, B);

    const int NB = B / BM;
    int nCTA = 0;
    for (int rb = 0; rb < NB; rb++) nCTA += (NB - rb + CHUNK - 1) / CHUNK;

    tile_kernel<<<nCTA, THREADS, SMEM_SZ>>>(labels, B);

    finalize_kernel<<<1, 1024>>>(B, out);
}

// round 16
// speedup vs baseline: 1.0813x; 1.0013x over previous
#include <cuda_runtime.h>
#include <cuda_fp16.h>
#include <math.h>
#include <stdint.h>

#define BMAX    8192
#define DDIM    128
#define MARGIN  0.5f
#define BM      128
#define BN      128
#define THREADS 256
#define NCTA    296           // 148 SMs x 2 resident CTAs

#define ENC_NEGINF 0x007FFFFFu   // enc(-inf)
#define ENC_POSINF 0xFF800000u   // enc(+inf)

// ---------------- device globals -------------------------------------------
__device__ __half g_hi[BMAX * DDIM];
__device__ float g_sqn[BMAX];
__device__ unsigned int g_posE[BMAX];
__device__ unsigned int g_negE[BMAX];

// ---------------- smem byte offsets ----------------------------------------
#define OFF_AHI    0            // 128*256 = 32768
#define OFF_B0     32768
#define OFF_B1     65536
#define OFF_META   98304        // 4 slots x 1024B (512 sq + 512 lbl)
#define OFF_COLP   102400       // 8*128 floats = 4096B
#define OFF_COLN   106496       // 4096B
#define SMEM_SZ    110592       // 108 KB -> 2 CTAs/SM

// ---------------- PTX helpers ----------------------------------------------
__device__ __forceinline__ uint32_t smem_u32(const void* p) {
    uint32_t a;
    asm("{ .reg .u64 t; cvta.to.shared.u64 t, %1; cvt.u32.u64 %0, t; }"
        : "=r"(a) : "l"(p));
    return a;
}
__device__ __forceinline__ void cpa16(uint32_t dst, const void* src) {
    asm volatile("cp.async.cg.shared.global [%0], [%1], 16;"
                 :: "r"(dst), "l"(__cvta_generic_to_global(src)));
}
__device__ __forceinline__ void cpa_commit() {
    asm volatile("cp.async.commit_group;" ::: "memory");
}
template <int N>
__device__ __forceinline__ void cpa_wait() {
    asm volatile("cp.async.wait_group %0;" :: "n"(N) : "memory");
}
__device__ __forceinline__ void ldsm4(uint32_t* r, uint32_t addr) {
    asm volatile("ldmatrix.sync.aligned.m8n8.x4.shared.b16 {%0,%1,%2,%3}, [%4];"
                 : "=r"(r[0]), "=r"(r[1]), "=r"(r[2]), "=r"(r[3]) : "r"(addr));
}
__device__ __forceinline__ void mma_f16(float* c, const uint32_t* a,
                                        const uint32_t* b) {
    asm volatile(
        "mma.sync.aligned.m16n8k16.row.col.f32.f16.f16.f32 "
        "{%0,%1,%2,%3}, {%4,%5,%6,%7}, {%8,%9}, {%0,%1,%2,%3};"
        : "+f"(c[0]), "+f"(c[1]), "+f"(c[2]), "+f"(c[3])
        : "r"(a[0]), "r"(a[1]), "r"(a[2]), "r"(a[3]), "r"(b[0]), "r"(b[1]));
}
__device__ __forceinline__ uint32_t swz(uint32_t base, int row, int c) {
    return base + (uint32_t)(row * 256) + (uint32_t)(((c ^ (row & 7)) << 4));
}
// order-preserving float<->uint encode for atomic max/min
__device__ __forceinline__ unsigned int encf(float f) {
    unsigned int u = __float_as_uint(f);
    return (u & 0x80000000u) ? ~u : (u | 0x80000000u);
}
__device__ __forceinline__ float decf(unsigned int e) {
    unsigned int u = (e & 0x80000000u) ? (e ^ 0x80000000u) : ~e;
    return __uint_as_float(u);
}

// ---------------------------------------------------------------------------
// Kernel 0: fp32 -> fp16 + squared norms (fp32) + result-buffer init.
// ---------------------------------------------------------------------------
__global__ void convert_kernel(const float* __restrict__ emb, int B) {
    int warp = (blockIdx.x * blockDim.x + threadIdx.x) >> 5;
    int lane = threadIdx.x & 31;
    if (warp >= B) return;
    const float4* row = (const float4*)(emb + (size_t)warp * DDIM);
    float4 v = row[lane];
    float s = v.x * v.x + v.y * v.y + v.z * v.z + v.w * v.w;
    #pragma unroll
    for (int off = 16; off; off >>= 1) s += __shfl_xor_sync(0xffffffffu, s, off);
    if (lane == 0) g_sqn[warp] = s;
    if (lane == 1) g_posE[warp] = ENC_NEGINF;
    if (lane == 2) g_negE[warp] = ENC_POSINF;

    __half2* hp = (__half2*)(g_hi + (size_t)warp * DDIM + lane * 4);
    hp[0] = __halves2half2(__float2half_rn(v.x), __float2half_rn(v.y));
    hp[1] = __halves2half2(__float2half_rn(v.z), __float2half_rn(v.w));
}

// ---------------------------------------------------------------------------
// Loaders (cp.async, swizzled B; metadata in its own 4-deep ring).
// ---------------------------------------------------------------------------
__device__ __forceinline__ void load_btile(uint32_t sbase, int which, int c0,
                                           int tid) {
    uint32_t off_b = which ? OFF_B1 : OFF_B0;
    #pragma unroll
    for (int i = 0; i < 8; i++) {
        int chunk = tid + i * THREADS;        // 0..2047
        int row = chunk >> 4;
        int c   = chunk & 15;
        cpa16(swz(sbase + off_b, row, c),
              g_hi + (size_t)(c0 + row) * DDIM + c * 8);
    }
}
__device__ __forceinline__ void load_meta(uint32_t sbase, int slot, int c0,
                                          const int* labels, int tid) {
    uint32_t mb = sbase + OFF_META + (uint32_t)slot * 1024u;
    if (tid < 32) {
        cpa16(mb + tid * 16, g_sqn + c0 + tid * 4);
    } else if (tid < 64) {
        int t = tid - 32;
        cpa16(mb + 512 + t * 16, labels + c0 + t * 4);
    }
}
__device__ __forceinline__ void load_arow(uint32_t sbase, int r0, int tid) {
    #pragma unroll
    for (int i = 0; i < 8; i++) {
        int chunk = tid + i * THREADS;
        int row = chunk >> 4;
        int c   = chunk & 15;
        cpa16(swz(sbase + OFF_AHI, row, c),
              g_hi + (size_t)(r0 + row) * DDIM + c * 8);
    }
}

// ---------------------------------------------------------------------------
// Kernel 1: balanced-run upper-triangle fp16 Gram + two-direction mining.
// Global tile order (rb asc, cb asc within row); CTA k owns the contiguous
// run [k*TT/grid, (k+1)*TT/grid) of 7-8 tiles. Row crossings reload A with
// an explicit pipeline drain (rare). 2 CTAs/SM.
// ---------------------------------------------------------------------------
__global__ __launch_bounds__(THREADS, 2)
void tile_kernel(const int* __restrict__ labels, int B) {
    extern __shared__ char smem[];
    const uint32_t sbase = smem_u32(smem);
    const int tid  = threadIdx.x;
    const int lane = tid & 31;
    const int wid  = tid >> 5;
    const int wm   = wid & 3;
    const int wn   = wid >> 2;
    const int NB   = B / BM;
    const int TT   = NB * (NB + 1) / 2;

    float* colP = (float*)(smem + OFF_COLP);
    float* colN = (float*)(smem + OFF_COLN);

    // ---- my contiguous run of global tile indices ----------------------
    const int k = blockIdx.x;
    const int gStart = (int)(((long long)k * TT) / gridDim.x);
    const int gEnd   = (int)(((long long)(k + 1) * TT) / gridDim.x);
    const int len = gEnd - gStart;
    if (len <= 0) return;

    int curRb = 0, base = 0;
    while (base + (NB - curRb) <= gStart) { base += NB - curRb; curRb++; }
    int curCb = curRb + (gStart - base);

    int nxtRb = curRb, nxtCb = curCb + 1;
    if (nxtCb == NB) { nxtRb++; nxtCb = nxtRb; }
    int nnRb = nxtRb, nnCb = nxtCb + 1;
    if (nnCb == NB) { nnRb++; nnCb = nnRb; }

    // ---- prologue: A(rb0) + B0 + M0 in group0; B1 + M1 in group1 -------
    load_arow(sbase, curRb * BM, tid);
    load_btile(sbase, 0, curCb * BN, tid);
    load_meta(sbase, 0, curCb * BN, labels, tid);
    cpa_commit();
    if (len > 1) {
        load_btile(sbase, 1, nxtCb * BN, tid);
        load_meta(sbase, 1, nxtCb * BN, labels, tid);
    }
    cpa_commit();

    const int g  = lane >> 2;
    const int t4 = lane & 3;
    const int aRow = (lane & 15);
    const int aCb  = (lane >> 4);
    const int bRow = (lane & 7) + ((lane >> 4) << 3);
    const int bCb  = (lane >> 3) & 1;
    const bool partialLane = ((lane & 12) == 0);       // g==0 or g==4
    const int partRow = wm * 2 + (lane >> 4);          // 0..7

    // ---- row-anchor state for curRb ------------------------------------
    int rowsG[4]; int labR[4]; float sqR[4];
    {
        int r0 = curRb * BM;
        #pragma unroll
        for (int s = 0; s < 4; s++) {
            int rl = wm * 32 + (s >> 1) * 16 + (s & 1) * 8 + g;
            rowsG[s] = r0 + rl;
            labR[s]  = labels[r0 + rl];
            sqR[s]   = g_sqn[r0 + rl];
        }
    }
    float pos[4], neg[4];
    #pragma unroll
    for (int s = 0; s < 4; s++) { pos[s] = -INFINITY; neg[s] = INFINITY; }

    bool waitAll = false;

    // ---- main loop over the run ----------------------------------------
    for (int t = 0; t < len; t++) {
        if (waitAll) cpa_wait<0>(); else cpa_wait<1>();
        __syncthreads();

        const uint32_t bBase = sbase + ((t & 1) ? OFF_B1 : OFF_B0);
        const float* sq_s  = (const float*)(smem + OFF_META + (t & 3) * 1024);
        const int*   lbl_s = (const int*)(smem + OFF_META + (t & 3) * 1024 + 512);
        const bool diag = (curCb == curRb);
        const int cg0 = curCb * BN;

        float acc[2][8][4];
        #pragma unroll
        for (int mi = 0; mi < 2; mi++)
            #pragma unroll
            for (int ni = 0; ni < 8; ni++)
                #pragma unroll
                for (int q = 0; q < 4; q++) acc[mi][ni][q] = 0.f;

        #pragma unroll
        for (int ks = 0; ks < 8; ks++) {
            uint32_t ahi[2][4], bhi[4][4];
            #pragma unroll
            for (int mi = 0; mi < 2; mi++) {
                int row = wm * 32 + mi * 16 + aRow;
                ldsm4(ahi[mi], swz(sbase + OFF_AHI, row, ks * 2 + aCb));
            }
            #pragma unroll
            for (int nj = 0; nj < 4; nj++) {
                int row = wn * 64 + nj * 16 + bRow;
                ldsm4(bhi[nj], swz(bBase, row, ks * 2 + bCb));
            }
            #pragma unroll
            for (int mi = 0; mi < 2; mi++)
                #pragma unroll
                for (int ni = 0; ni < 8; ni++)
                    mma_f16(acc[mi][ni], ahi[mi], &bhi[ni >> 1][(ni & 1) * 2]);
        }

        // all A/B reads of tile t done; safe to prefetch t+2 and (on a
        // row crossing) the next row's A tile.
        __syncthreads();
        const bool crossNext = (t + 1 < len) && (nxtRb != curRb);
        if (t + 2 < len) {
            load_btile(sbase, (t + 2) & 1, nnCb * BN, tid);
            load_meta(sbase, (t + 2) & 3, nnCb * BN, labels, tid);
        }
        if (crossNext) load_arow(sbase, nxtRb * BM, tid);
        cpa_commit();   // exactly one group per iteration
        waitAll = crossNext;    // A sits in the newest group -> full drain

        if (diag) {
            // ---- diagonal tile: row mining only, with self-exclusion ---
            #pragma unroll
            for (int ni = 0; ni < 8; ni++) {
                int colLoc = wn * 64 + ni * 8 + t4 * 2;
                float sq0 = sq_s[colLoc], sq1 = sq_s[colLoc + 1];
                int   l0  = lbl_s[colLoc], l1 = lbl_s[colLoc + 1];
                int   j0  = cg0 + colLoc;
                #pragma unroll
                for (int s = 0; s < 4; s++) {
                    float v0 = fmaf(-2.f, acc[s >> 1][ni][(s & 1) * 2], sq0);
                    float v1 = fmaf(-2.f, acc[s >> 1][ni][(s & 1) * 2 + 1], sq1);
                    if (l0 == labR[s]) {
                        if (j0 != rowsG[s]) pos[s] = fmaxf(pos[s], v0);
                    } else neg[s] = fminf(neg[s], v0);
                    if (l1 == labR[s]) {
                        if (j0 + 1 != rowsG[s]) pos[s] = fmaxf(pos[s], v1);
                    } else neg[s] = fminf(neg[s], v1);
                }
            }
        } else {
            // ---- off-diagonal: merged row+col mining, 2-stage shfl,
            //      8 partial rows to smem, single atomic per column.
            #pragma unroll
            for (int ni = 0; ni < 8; ni++) {
                #pragma unroll
                for (int v = 0; v < 2; v++) {
                    int colLoc = wn * 64 + ni * 8 + t4 * 2 + v;
                    float sqj = sq_s[colLoc];
                    int   lj  = lbl_s[colLoc];
                    float cp = -INFINITY, cn = INFINITY;
                    #pragma unroll
                    for (int s = 0; s < 4; s++) {
                        float a = acc[s >> 1][ni][(s & 1) * 2 + v];
                        float vrow = fmaf(-2.f, a, sqj);
                        float vcol = fmaf(-2.f, a, sqR[s]);
                        if (lj == labR[s]) {
                            pos[s] = fmaxf(pos[s], vrow);
                            cp = fmaxf(cp, vcol);
                        } else {
                            neg[s] = fminf(neg[s], vrow);
                            cn = fminf(cn, vcol);
                        }
                    }
                    cp = fmaxf(cp, __shfl_xor_sync(0xffffffffu, cp, 4));
                    cn = fminf(cn, __shfl_xor_sync(0xffffffffu, cn, 4));
                    cp = fmaxf(cp, __shfl_xor_sync(0xffffffffu, cp, 8));
                    cn = fminf(cn, __shfl_xor_sync(0xffffffffu, cn, 8));
                    if (partialLane) {          // lanes g==0 and g==4
                        colP[partRow * 128 + colLoc] = cp;
                        colN[partRow * 128 + colLoc] = cn;
                    }
                }
            }
            __syncthreads();
            if (tid < 128) {
                float p = colP[tid];
                #pragma unroll
                for (int w = 1; w < 8; w++)
                    p = fmaxf(p, colP[w * 128 + tid]);
                atomicMax(&g_posE[cg0 + tid], encf(p));
            } else {
                int c = tid - 128;
                float n = colN[c];
                #pragma unroll
                for (int w = 1; w < 8; w++)
                    n = fminf(n, colN[w * 128 + c]);
                atomicMin(&g_negE[cg0 + c], encf(n));
            }
        }

        // ---- row crossing: flush curRb results, load nxtRb state -------
        if (crossNext) {
            #pragma unroll
            for (int s = 0; s < 4; s++) {
                #pragma unroll
                for (int off = 1; off < 4; off <<= 1) {
                    pos[s] = fmaxf(pos[s], __shfl_xor_sync(0xffffffffu, pos[s], off));
                    neg[s] = fminf(neg[s], __shfl_xor_sync(0xffffffffu, neg[s], off));
                }
            }
            if (t4 == 0) {
                #pragma unroll
                for (int s = 0; s < 4; s++) {
                    atomicMax(&g_posE[rowsG[s]], encf(pos[s]));
                    atomicMin(&g_negE[rowsG[s]], encf(neg[s]));
                }
            }
            int r0 = nxtRb * BM;
            #pragma unroll
            for (int s = 0; s < 4; s++) {
                int rl = wm * 32 + (s >> 1) * 16 + (s & 1) * 8 + g;
                rowsG[s] = r0 + rl;
                labR[s]  = labels[r0 + rl];
                sqR[s]   = g_sqn[r0 + rl];
                pos[s] = -INFINITY;
                neg[s] = INFINITY;
            }
        }

        // advance (cur, nxt, nn)
        curRb = nxtRb; curCb = nxtCb;
        nxtRb = nnRb;  nxtCb = nnCb;
        nnCb++; if (nnCb == NB) { nnRb++; nnCb = nnRb; }
    }

    // ---- final flush for the last row segment ---------------------------
    #pragma unroll
    for (int s = 0; s < 4; s++) {
        #pragma unroll
        for (int off = 1; off < 4; off <<= 1) {
            pos[s] = fmaxf(pos[s], __shfl_xor_sync(0xffffffffu, pos[s], off));
            neg[s] = fminf(neg[s], __shfl_xor_sync(0xffffffffu, neg[s], off));
        }
    }
    if (t4 == 0) {
        #pragma unroll
        for (int s = 0; s < 4; s++) {
            atomicMax(&g_posE[rowsG[s]], encf(pos[s]));
            atomicMin(&g_negE[rowsG[s]], encf(neg[s]));
        }
    }
}

// ---------------------------------------------------------------------------
// Kernel 2: decode, per-anchor loss, global mean.
// ---------------------------------------------------------------------------
__global__ void finalize_kernel(int B, float* __restrict__ out) {
    __shared__ float ssum[1024];
    __shared__ float scnt[1024];
    int tid = threadIdx.x;
    float sum = 0.f, cnt = 0.f;
    for (int r = tid; r < B; r += 1024) {
        float p = decf(g_posE[r]);
        float n = decf(g_negE[r]);
        bool valid = (p != -INFINITY) && (n != INFINITY);
        float sq = g_sqn[r];
        float hp = sqrtf(fmaxf(sq + p, 0.f));
        float hn = sqrtf(fmaxf(sq + n, 0.f));
        float per = fmaxf(hp - hn + MARGIN, 0.f);
        if (valid) { sum += per; cnt += 1.f; }
    }
    ssum[tid] = sum;
    scnt[tid] = cnt;
    __syncthreads();
    for (int s = 512; s; s >>= 1) {
        if (tid < s) { ssum[tid] += ssum[tid + s]; scnt[tid] += scnt[tid + s]; }
        __syncthreads();
    }
    if (tid == 0) out[0] = ssum[0] / fmaxf(scnt[0], 1.f);
}

// ---------------------------------------------------------------------------
extern "C" void kernel_launch(void* const* d_in, const int* in_sizes, int n_in,
                              void* d_out, int out_size) {
    const float* emb    = (const float*)d_in[0];
    const int*   labels = (const int*)d_in[1];
    const int B = in_sizes[1];                   // 8192
    float* out = (float*)d_out;

    cudaFuncSetAttribute(tile_kernel,
                         cudaFuncAttributeMaxDynamicSharedMemorySize, SMEM_SZ);

    convert_kernel<<<(B * 32 + 255) / 256, 256>>>(emb, B);

    const int NB = B / BM;
    const int TT = NB * (NB + 1) / 2;
    int grid = TT < NCTA ? TT : NCTA;
    tile_kernel<<<grid, THREADS, SMEM_SZ>>>(labels, B);

    finalize_kernel<<<1, 1024>>>(B, out);
}

// round 17
// speedup vs baseline: 1.0898x; 1.0078x over previous
#include <cuda_runtime.h>
#include <cuda_fp16.h>
#include <math.h>
#include <stdint.h>

#define BMAX    8192
#define DDIM    128
#define MARGIN  0.5f
#define BM      128
#define BN      128
#define THREADS 256
#define NCTA    296           // 148 SMs x 2 resident CTAs

#define ENC_NEGINF 0x007FFFFFu   // enc(-inf)
#define ENC_POSINF 0xFF800000u   // enc(+inf)

// ---------------- device globals -------------------------------------------
__device__ __half g_hi[BMAX * DDIM];
__device__ float g_sqn[BMAX];
__device__ unsigned int g_posE[BMAX];
__device__ unsigned int g_negE[BMAX];

// ---------------- smem byte offsets ----------------------------------------
#define OFF_AHI    0            // 128*256 = 32768
#define OFF_B0     32768
#define OFF_B1     65536
#define OFF_META   98304        // 4 slots x 1024B (512 sq + 512 lbl)
#define OFF_COLP   102400       // 8*128 floats = 4096B
#define OFF_COLN   106496       // 4096B
#define SMEM_SZ    110592       // 108 KB -> 2 CTAs/SM

// ---------------- PTX helpers ----------------------------------------------
__device__ __forceinline__ uint32_t smem_u32(const void* p) {
    uint32_t a;
    asm("{ .reg .u64 t; cvta.to.shared.u64 t, %1; cvt.u32.u64 %0, t; }"
        : "=r"(a) : "l"(p));
    return a;
}
__device__ __forceinline__ void cpa16(uint32_t dst, const void* src) {
    asm volatile("cp.async.cg.shared.global [%0], [%1], 16;"
                 :: "r"(dst), "l"(__cvta_generic_to_global(src)));
}
__device__ __forceinline__ void cpa_commit() {
    asm volatile("cp.async.commit_group;" ::: "memory");
}
template <int N>
__device__ __forceinline__ void cpa_wait() {
    asm volatile("cp.async.wait_group %0;" :: "n"(N) : "memory");
}
__device__ __forceinline__ void ldsm4(uint32_t* r, uint32_t addr) {
    asm volatile("ldmatrix.sync.aligned.m8n8.x4.shared.b16 {%0,%1,%2,%3}, [%4];"
                 : "=r"(r[0]), "=r"(r[1]), "=r"(r[2]), "=r"(r[3]) : "r"(addr));
}
__device__ __forceinline__ void mma_f16(float* c, const uint32_t* a,
                                        const uint32_t* b) {
    asm volatile(
        "mma.sync.aligned.m16n8k16.row.col.f32.f16.f16.f32 "
        "{%0,%1,%2,%3}, {%4,%5,%6,%7}, {%8,%9}, {%0,%1,%2,%3};"
        : "+f"(c[0]), "+f"(c[1]), "+f"(c[2]), "+f"(c[3])
        : "r"(a[0]), "r"(a[1]), "r"(a[2]), "r"(a[3]), "r"(b[0]), "r"(b[1]));
}
__device__ __forceinline__ uint32_t swz(uint32_t base, int row, int c) {
    return base + (uint32_t)(row * 256) + (uint32_t)(((c ^ (row & 7)) << 4));
}
// order-preserving float<->uint encode for atomic max/min
__device__ __forceinline__ unsigned int encf(float f) {
    unsigned int u = __float_as_uint(f);
    return (u & 0x80000000u) ? ~u : (u | 0x80000000u);
}
__device__ __forceinline__ float decf(unsigned int e) {
    unsigned int u = (e & 0x80000000u) ? (e ^ 0x80000000u) : ~e;
    return __uint_as_float(u);
}

// ---------------------------------------------------------------------------
// Kernel 0: fp32 -> fp16 + squared norms + result-buffer init.
// Each warp processes 4 rows (spaced B/4) with all loads issued up front
// (MLP=4) so DRAM latency overlaps.
// ---------------------------------------------------------------------------
__global__ void convert_kernel(const float* __restrict__ emb, int B) {
    int warp = (blockIdx.x * blockDim.x + threadIdx.x) >> 5;
    int lane = threadIdx.x & 31;
    int quarter = B >> 2;
    if (warp >= quarter) return;

    float4 v[4];
    #pragma unroll
    for (int r = 0; r < 4; r++) {
        const float4* row =
            (const float4*)(emb + (size_t)(warp + r * quarter) * DDIM);
        v[r] = row[lane];
    }
    float s[4];
    #pragma unroll
    for (int r = 0; r < 4; r++)
        s[r] = v[r].x * v[r].x + v[r].y * v[r].y
             + v[r].z * v[r].z + v[r].w * v[r].w;
    #pragma unroll
    for (int off = 16; off; off >>= 1)
        #pragma unroll
        for (int r = 0; r < 4; r++)
            s[r] += __shfl_xor_sync(0xffffffffu, s[r], off);

    #pragma unroll
    for (int r = 0; r < 4; r++) {
        int rowIdx = warp + r * quarter;
        if (lane == 0) g_sqn[rowIdx] = s[r];
        if (lane == 1) g_posE[rowIdx] = ENC_NEGINF;
        if (lane == 2) g_negE[rowIdx] = ENC_POSINF;
        __half2* hp = (__half2*)(g_hi + (size_t)rowIdx * DDIM + lane * 4);
        hp[0] = __halves2half2(__float2half_rn(v[r].x), __float2half_rn(v[r].y));
        hp[1] = __halves2half2(__float2half_rn(v[r].z), __float2half_rn(v[r].w));
    }
}

// ---------------------------------------------------------------------------
// Loaders (cp.async, swizzled B; metadata in its own 4-deep ring).
// ---------------------------------------------------------------------------
__device__ __forceinline__ void load_btile(uint32_t sbase, int which, int c0,
                                           int tid) {
    uint32_t off_b = which ? OFF_B1 : OFF_B0;
    #pragma unroll
    for (int i = 0; i < 8; i++) {
        int chunk = tid + i * THREADS;        // 0..2047
        int row = chunk >> 4;
        int c   = chunk & 15;
        cpa16(swz(sbase + off_b, row, c),
              g_hi + (size_t)(c0 + row) * DDIM + c * 8);
    }
}
__device__ __forceinline__ void load_meta(uint32_t sbase, int slot, int c0,
                                          const int* labels, int tid) {
    uint32_t mb = sbase + OFF_META + (uint32_t)slot * 1024u;
    if (tid < 32) {
        cpa16(mb + tid * 16, g_sqn + c0 + tid * 4);
    } else if (tid < 64) {
        int t = tid - 32;
        cpa16(mb + 512 + t * 16, labels + c0 + t * 4);
    }
}
__device__ __forceinline__ void load_arow(uint32_t sbase, int r0, int tid) {
    #pragma unroll
    for (int i = 0; i < 8; i++) {
        int chunk = tid + i * THREADS;
        int row = chunk >> 4;
        int c   = chunk & 15;
        cpa16(swz(sbase + OFF_AHI, row, c),
              g_hi + (size_t)(r0 + row) * DDIM + c * 8);
    }
}

// ---------------------------------------------------------------------------
// Kernel 1: balanced-run upper-triangle fp16 Gram + two-direction mining.
// Global tile order (rb asc, cb asc within row); CTA k owns the contiguous
// run [k*TT/grid, (k+1)*TT/grid) of 7-8 tiles. Row crossings reload A with
// an explicit pipeline drain (rare). 2 CTAs/SM.
// ---------------------------------------------------------------------------
__global__ __launch_bounds__(THREADS, 2)
void tile_kernel(const int* __restrict__ labels, int B) {
    extern __shared__ char smem[];
    const uint32_t sbase = smem_u32(smem);
    const int tid  = threadIdx.x;
    const int lane = tid & 31;
    const int wid  = tid >> 5;
    const int wm   = wid & 3;
    const int wn   = wid >> 2;
    const int NB   = B / BM;
    const int TT   = NB * (NB + 1) / 2;

    float* colP = (float*)(smem + OFF_COLP);
    float* colN = (float*)(smem + OFF_COLN);

    // ---- my contiguous run of global tile indices ----------------------
    const int k = blockIdx.x;
    const int gStart = (int)(((long long)k * TT) / gridDim.x);
    const int gEnd   = (int)(((long long)(k + 1) * TT) / gridDim.x);
    const int len = gEnd - gStart;
    if (len <= 0) return;

    int curRb = 0, base = 0;
    while (base + (NB - curRb) <= gStart) { base += NB - curRb; curRb++; }
    int curCb = curRb + (gStart - base);

    int nxtRb = curRb, nxtCb = curCb + 1;
    if (nxtCb == NB) { nxtRb++; nxtCb = nxtRb; }
    int nnRb = nxtRb, nnCb = nxtCb + 1;
    if (nnCb == NB) { nnRb++; nnCb = nnRb; }

    // ---- prologue: A(rb0) + B0 + M0 in group0; B1 + M1 in group1 -------
    load_arow(sbase, curRb * BM, tid);
    load_btile(sbase, 0, curCb * BN, tid);
    load_meta(sbase, 0, curCb * BN, labels, tid);
    cpa_commit();
    if (len > 1) {
        load_btile(sbase, 1, nxtCb * BN, tid);
        load_meta(sbase, 1, nxtCb * BN, labels, tid);
    }
    cpa_commit();

    const int g  = lane >> 2;
    const int t4 = lane & 3;
    const int aRow = (lane & 15);
    const int aCb  = (lane >> 4);
    const int bRow = (lane & 7) + ((lane >> 4) << 3);
    const int bCb  = (lane >> 3) & 1;
    const bool partialLane = ((lane & 12) == 0);       // g==0 or g==4
    const int partRow = wm * 2 + (lane >> 4);          // 0..7

    // ---- row-anchor state for curRb ------------------------------------
    int rowsG[4]; int labR[4]; float sqR[4];
    {
        int r0 = curRb * BM;
        #pragma unroll
        for (int s = 0; s < 4; s++) {
            int rl = wm * 32 + (s >> 1) * 16 + (s & 1) * 8 + g;
            rowsG[s] = r0 + rl;
            labR[s]  = labels[r0 + rl];
            sqR[s]   = g_sqn[r0 + rl];
        }
    }
    float pos[4], neg[4];
    #pragma unroll
    for (int s = 0; s < 4; s++) { pos[s] = -INFINITY; neg[s] = INFINITY; }

    bool waitAll = false;

    // ---- main loop over the run ----------------------------------------
    for (int t = 0; t < len; t++) {
        if (waitAll) cpa_wait<0>(); else cpa_wait<1>();
        __syncthreads();

        const uint32_t bBase = sbase + ((t & 1) ? OFF_B1 : OFF_B0);
        const float* sq_s  = (const float*)(smem + OFF_META + (t & 3) * 1024);
        const int*   lbl_s = (const int*)(smem + OFF_META + (t & 3) * 1024 + 512);
        const bool diag = (curCb == curRb);
        const int cg0 = curCb * BN;

        float acc[2][8][4];
        #pragma unroll
        for (int mi = 0; mi < 2; mi++)
            #pragma unroll
            for (int ni = 0; ni < 8; ni++)
                #pragma unroll
                for (int q = 0; q < 4; q++) acc[mi][ni][q] = 0.f;

        #pragma unroll
        for (int ks = 0; ks < 8; ks++) {
            uint32_t ahi[2][4], bhi[4][4];
            #pragma unroll
            for (int mi = 0; mi < 2; mi++) {
                int row = wm * 32 + mi * 16 + aRow;
                ldsm4(ahi[mi], swz(sbase + OFF_AHI, row, ks * 2 + aCb));
            }
            #pragma unroll
            for (int nj = 0; nj < 4; nj++) {
                int row = wn * 64 + nj * 16 + bRow;
                ldsm4(bhi[nj], swz(bBase, row, ks * 2 + bCb));
            }
            #pragma unroll
            for (int mi = 0; mi < 2; mi++)
                #pragma unroll
                for (int ni = 0; ni < 8; ni++)
                    mma_f16(acc[mi][ni], ahi[mi], &bhi[ni >> 1][(ni & 1) * 2]);
        }

        // all A/B reads of tile t done; safe to prefetch t+2 and (on a
        // row crossing) the next row's A tile.
        __syncthreads();
        const bool crossNext = (t + 1 < len) && (nxtRb != curRb);
        if (t + 2 < len) {
            load_btile(sbase, (t + 2) & 1, nnCb * BN, tid);
            load_meta(sbase, (t + 2) & 3, nnCb * BN, labels, tid);
        }
        if (crossNext) load_arow(sbase, nxtRb * BM, tid);
        cpa_commit();   // exactly one group per iteration
        waitAll = crossNext;    // A sits in the newest group -> full drain

        if (diag) {
            // ---- diagonal tile: row mining only, with self-exclusion ---
            #pragma unroll
            for (int ni = 0; ni < 8; ni++) {
                int colLoc = wn * 64 + ni * 8 + t4 * 2;
                float2 sqj2 = *(const float2*)(sq_s + colLoc);
                int2   lj2  = *(const int2*)(lbl_s + colLoc);
                int    j0   = cg0 + colLoc;
                #pragma unroll
                for (int s = 0; s < 4; s++) {
                    float v0 = fmaf(-2.f, acc[s >> 1][ni][(s & 1) * 2], sqj2.x);
                    float v1 = fmaf(-2.f, acc[s >> 1][ni][(s & 1) * 2 + 1], sqj2.y);
                    if (lj2.x == labR[s]) {
                        if (j0 != rowsG[s]) pos[s] = fmaxf(pos[s], v0);
                    } else neg[s] = fminf(neg[s], v0);
                    if (lj2.y == labR[s]) {
                        if (j0 + 1 != rowsG[s]) pos[s] = fmaxf(pos[s], v1);
                    } else neg[s] = fminf(neg[s], v1);
                }
            }
        } else {
            // ---- off-diagonal: merged row+col mining, 2-stage shfl,
            //      vectorized meta loads + fused STS.64 partial writes.
            #pragma unroll
            for (int ni = 0; ni < 8; ni++) {
                int colLoc = wn * 64 + ni * 8 + t4 * 2;
                float2 sqj2 = *(const float2*)(sq_s + colLoc);
                int2   lj2  = *(const int2*)(lbl_s + colLoc);
                float cp0 = -INFINITY, cn0 = INFINITY;
                float cp1 = -INFINITY, cn1 = INFINITY;
                #pragma unroll
                for (int s = 0; s < 4; s++) {
                    float a0 = acc[s >> 1][ni][(s & 1) * 2];
                    float a1 = acc[s >> 1][ni][(s & 1) * 2 + 1];
                    float vr0 = fmaf(-2.f, a0, sqj2.x);
                    float vc0 = fmaf(-2.f, a0, sqR[s]);
                    float vr1 = fmaf(-2.f, a1, sqj2.y);
                    float vc1 = fmaf(-2.f, a1, sqR[s]);
                    if (lj2.x == labR[s]) {
                        pos[s] = fmaxf(pos[s], vr0);
                        cp0 = fmaxf(cp0, vc0);
                    } else {
                        neg[s] = fminf(neg[s], vr0);
                        cn0 = fminf(cn0, vc0);
                    }
                    if (lj2.y == labR[s]) {
                        pos[s] = fmaxf(pos[s], vr1);
                        cp1 = fmaxf(cp1, vc1);
                    } else {
                        neg[s] = fminf(neg[s], vr1);
                        cn1 = fminf(cn1, vc1);
                    }
                }
                cp0 = fmaxf(cp0, __shfl_xor_sync(0xffffffffu, cp0, 4));
                cn0 = fminf(cn0, __shfl_xor_sync(0xffffffffu, cn0, 4));
                cp1 = fmaxf(cp1, __shfl_xor_sync(0xffffffffu, cp1, 4));
                cn1 = fminf(cn1, __shfl_xor_sync(0xffffffffu, cn1, 4));
                cp0 = fmaxf(cp0, __shfl_xor_sync(0xffffffffu, cp0, 8));
                cn0 = fminf(cn0, __shfl_xor_sync(0xffffffffu, cn0, 8));
                cp1 = fmaxf(cp1, __shfl_xor_sync(0xffffffffu, cp1, 8));
                cn1 = fminf(cn1, __shfl_xor_sync(0xffffffffu, cn1, 8));
                if (partialLane) {          // lanes g==0 and g==4
                    *(float2*)(colP + partRow * 128 + colLoc) =
                        make_float2(cp0, cp1);
                    *(float2*)(colN + partRow * 128 + colLoc) =
                        make_float2(cn0, cn1);
                }
            }
            __syncthreads();
            if (tid < 128) {
                float p = colP[tid];
                #pragma unroll
                for (int w = 1; w < 8; w++)
                    p = fmaxf(p, colP[w * 128 + tid]);
                atomicMax(&g_posE[cg0 + tid], encf(p));
            } else {
                int c = tid - 128;
                float n = colN[c];
                #pragma unroll
                for (int w = 1; w < 8; w++)
                    n = fminf(n, colN[w * 128 + c]);
                atomicMin(&g_negE[cg0 + c], encf(n));
            }
        }

        // ---- row crossing: flush curRb results, load nxtRb state -------
        if (crossNext) {
            #pragma unroll
            for (int s = 0; s < 4; s++) {
                #pragma unroll
                for (int off = 1; off < 4; off <<= 1) {
                    pos[s] = fmaxf(pos[s], __shfl_xor_sync(0xffffffffu, pos[s], off));
                    neg[s] = fminf(neg[s], __shfl_xor_sync(0xffffffffu, neg[s], off));
                }
            }
            if (t4 == 0) {
                #pragma unroll
                for (int s = 0; s < 4; s++) {
                    atomicMax(&g_posE[rowsG[s]], encf(pos[s]));
                    atomicMin(&g_negE[rowsG[s]], encf(neg[s]));
                }
            }
            int r0 = nxtRb * BM;
            #pragma unroll
            for (int s = 0; s < 4; s++) {
                int rl = wm * 32 + (s >> 1) * 16 + (s & 1) * 8 + g;
                rowsG[s] = r0 + rl;
                labR[s]  = labels[r0 + rl];
                sqR[s]   = g_sqn[r0 + rl];
                pos[s] = -INFINITY;
                neg[s] = INFINITY;
            }
        }

        // advance (cur, nxt, nn)
        curRb = nxtRb; curCb = nxtCb;
        nxtRb = nnRb;  nxtCb = nnCb;
        nnCb++; if (nnCb == NB) { nnRb++; nnCb = nnRb; }
    }

    // ---- final flush for the last row segment ---------------------------
    #pragma unroll
    for (int s = 0; s < 4; s++) {
        #pragma unroll
        for (int off = 1; off < 4; off <<= 1) {
            pos[s] = fmaxf(pos[s], __shfl_xor_sync(0xffffffffu, pos[s], off));
            neg[s] = fminf(neg[s], __shfl_xor_sync(0xffffffffu, neg[s], off));
        }
    }
    if (t4 == 0) {
        #pragma unroll
        for (int s = 0; s < 4; s++) {
            atomicMax(&g_posE[rowsG[s]], encf(pos[s]));
            atomicMin(&g_negE[rowsG[s]], encf(neg[s]));
        }
    }
}

// ---------------------------------------------------------------------------
// Kernel 2: decode, per-anchor loss, global mean.
// ---------------------------------------------------------------------------
__global__ void finalize_kernel(int B, float* __restrict__ out) {
    __shared__ float ssum[1024];
    __shared__ float scnt[1024];
    int tid = threadIdx.x;
    float sum = 0.f, cnt = 0.f;
    for (int r = tid; r < B; r += 1024) {
        float p = decf(g_posE[r]);
        float n = decf(g_negE[r]);
        bool valid = (p != -INFINITY) && (n != INFINITY);
        float sq = g_sqn[r];
        float hp = sqrtf(fmaxf(sq + p, 0.f));
        float hn = sqrtf(fmaxf(sq + n, 0.f));
        float per = fmaxf(hp - hn + MARGIN, 0.f);
        if (valid) { sum += per; cnt += 1.f; }
    }
    ssum[tid] = sum;
    scnt[tid] = cnt;
    __syncthreads();
    for (int s = 512; s; s >>= 1) {
        if (tid < s) { ssum[tid] += ssum[tid + s]; scnt[tid] += scnt[tid + s]; }
        __syncthreads();
    }
    if (tid == 0) out[0] = ssum[0] / fmaxf(scnt[0], 1.f);
}

// ---------------------------------------------------------------------------
extern "C" void kernel_launch(void* const* d_in, const int* in_sizes, int n_in,
                              void* d_out, int out_size) {
    const float* emb    = (const float*)d_in[0];
    const int*   labels = (const int*)d_in[1];
    const int B = in_sizes[1];                   // 8192
    float* out = (float*)d_out;

    cudaFuncSetAttribute(tile_kernel,
                         cudaFuncAttributeMaxDynamicSharedMemorySize, SMEM_SZ);

    // B/4 warps, each handling 4 rows (MLP=4)
    convert_kernel<<<(B / 4 * 32 + 255) / 256, 256>>>(emb, B);

    const int NB = B / BM;
    const int TT = NB * (NB + 1) / 2;
    int grid = TT < NCTA ? TT : NCTA;
    tile_kernel<<<grid, THREADS, SMEM_SZ>>>(labels, B);

    finalize_kernel<<<1, 1024>>>(B, out);
}